// round 9
// baseline (speedup 1.0000x reference)
#include <cuda_runtime.h>
#include <cuda_bf16.h>
#include <cstdint>

#define H      256
#define NMAX   8192
#define NCLS   6        // classes 1..6; confused pair of c is c^1 (0-based)
#define TAJ    128      // anchors per job (M)
#define TBJ    64       // cols per job (N)
#define KCH    64       // K elements per staged chunk
#define NCH    4        // chunks per job
#define MAT_A  16384    // bytes per A matrix chunk: 128 rows x 128 B
#define MAT_Bb 8192     // bytes per B matrix chunk: 64 rows x 128 B
#define BUF_B  (2 * MAT_A + 2 * MAT_Bb)   // Ah,Al,Bh,Bl = 48 KB
#define DSMEM  (2 * BUF_B + 1024)         // double-buffered + align slack

// ---- scratch (static device globals; no dynamic allocation) ----
__device__ __nv_bfloat16 g_eh[NMAX * H];   // hi bf16 of normalized embeddings
__device__ __nv_bfloat16 g_el[NMAX * H];   // lo residual bf16
__device__ int      g_idx[NCLS][NMAX];
__device__ int      g_cnt[NCLS];
__device__ unsigned g_posmin[NMAX];
__device__ unsigned g_negmax[NMAX];
__device__ int      g_ticket;

__device__ __forceinline__ unsigned enc_f(float f) {
    unsigned u = __float_as_uint(f);
    return (u & 0x80000000u) ? ~u : (u | 0x80000000u);
}
__device__ __forceinline__ float dec_f(unsigned v) {
    return __uint_as_float((v & 0x80000000u) ? (v ^ 0x80000000u) : ~v);
}
__device__ __forceinline__ uint32_t smem_u32(const void* p) {
    uint32_t a;
    asm("{ .reg .u64 t; cvta.to.shared.u64 t, %1; cvt.u32.u64 %0, t; }" : "=r"(a) : "l"(p));
    return a;
}
// per-block label dtype sniff: 1 if int64, 0 if int32
__device__ __forceinline__ int sniff_lab64(const void* labv, int N) {
    const long long* l = reinterpret_cast<const long long*>(labv);
    int n = (N < 16) ? N : 16;
    int ok = 1;
    for (int i = 0; i < n; i++) {
        long long v = l[i];
        if (v < -1000000LL || v > 1000000LL) ok = 0;
    }
    return ok;
}
__device__ __forceinline__ long long load_lab(const void* labv, int lab64, int i) {
    return lab64 ? reinterpret_cast<const long long*>(labv)[i]
                 : (long long)reinterpret_cast<const int*>(labv)[i];
}

#define LDSM_X4(r0, r1, r2, r3, addr) \
    asm volatile("ldmatrix.sync.aligned.m8n8.x4.shared.b16 {%0,%1,%2,%3}, [%4];" \
        : "=r"(r0), "=r"(r1), "=r"(r2), "=r"(r3) : "r"(addr))

#define MMA16816(d, a, b) \
    asm volatile("mma.sync.aligned.m16n8k16.row.col.f32.bf16.bf16.f32 " \
        "{%0,%1,%2,%3}, {%4,%5,%6,%7}, {%8,%9}, {%0,%1,%2,%3};" \
        : "+f"((d)[0]), "+f"((d)[1]), "+f"((d)[2]), "+f"((d)[3]) \
        : "r"((a)[0]), "r"((a)[1]), "r"((a)[2]), "r"((a)[3]), \
          "r"((b)[0]), "r"((b)[1]))

#define CP_ASYNC16(dst, src, srcsize) \
    asm volatile("cp.async.cg.shared.global [%0], [%1], 16, %2;" \
        :: "r"(dst), "l"(src), "r"(srcsize) : "memory")
#define CP_COMMIT()  asm volatile("cp.async.commit_group;" ::: "memory")
#define CP_WAIT(n)   asm volatile("cp.async.wait_group %0;" :: "n"(n) : "memory")

// ---- K1: L2-normalize rows, emit bf16 hi/lo, init min/max; block 0 zeroes counters ----
__global__ void k_norm(const float* __restrict__ emb, int N) {
    if (blockIdx.x == 0) {
        int t = threadIdx.x;
        if (t < NCLS) g_cnt[t] = 0;
        if (t == 30) g_ticket = 0;
    }
    int row  = blockIdx.x * 8 + (threadIdx.x >> 5);
    int lane = threadIdx.x & 31;
    if (row >= N) return;
    const float4* src = reinterpret_cast<const float4*>(emb) + row * (H / 4);
    float4 v0 = src[lane * 2];
    float4 v1 = src[lane * 2 + 1];
    float ss = v0.x*v0.x + v0.y*v0.y + v0.z*v0.z + v0.w*v0.w
             + v1.x*v1.x + v1.y*v1.y + v1.z*v1.z + v1.w*v1.w;
#pragma unroll
    for (int o = 16; o; o >>= 1) ss += __shfl_xor_sync(0xffffffffu, ss, o);
    float s = 1.0f / fmaxf(sqrtf(ss), 1e-12f);
    float f[8] = { v0.x*s, v0.y*s, v0.z*s, v0.w*s, v1.x*s, v1.y*s, v1.z*s, v1.w*s };
    unsigned hw[4], lw[4];
#pragma unroll
    for (int p = 0; p < 4; p++) {
        float a = f[2*p], b = f[2*p+1];
        __nv_bfloat16 ha = __float2bfloat16_rn(a);
        __nv_bfloat16 hb = __float2bfloat16_rn(b);
        __nv_bfloat16 la = __float2bfloat16_rn(a - __bfloat162float(ha));
        __nv_bfloat16 lb = __float2bfloat16_rn(b - __bfloat162float(hb));
        hw[p] = (unsigned)__bfloat16_as_ushort(ha) | ((unsigned)__bfloat16_as_ushort(hb) << 16);
        lw[p] = (unsigned)__bfloat16_as_ushort(la) | ((unsigned)__bfloat16_as_ushort(lb) << 16);
    }
    reinterpret_cast<uint4*>(g_eh)[row * (H / 8) + lane] = make_uint4(hw[0], hw[1], hw[2], hw[3]);
    reinterpret_cast<uint4*>(g_el)[row * (H / 8) + lane] = make_uint4(lw[0], lw[1], lw[2], lw[3]);
    if (lane == 0) {
        g_posmin[row] = enc_f(1e9f);
        g_negmax[row] = enc_f(-1e9f);
    }
}

// ---- K2: compact row indices per class, block-aggregated atomics ----
__global__ void k_compact(const void* __restrict__ labv, int N) {
    __shared__ int hcnt[NCLS];
    __shared__ int hbase[NCLS];
    int tid = threadIdx.x;
    int lab64 = sniff_lab64(labv, N);
    if (tid < NCLS) hcnt[tid] = 0;
    __syncthreads();
    int i = blockIdx.x * 256 + tid;
    int c = -1, p = 0;
    if (i < N) {
        long long l = load_lab(labv, lab64, i);
        if (l >= 1 && l <= 6) {
            c = (int)l - 1;
            p = atomicAdd(&hcnt[c], 1);
        }
    }
    __syncthreads();
    if (tid < NCLS) hbase[tid] = hcnt[tid] ? atomicAdd(&g_cnt[tid], hcnt[tid]) : 0;
    __syncthreads();
    if (c >= 0) g_idx[c][hbase[c] + p] = i;
}

// ---- K3: persistent HMMA GEMM, cp.async double-buffered, 2 CTAs/SM ----
// Job = (class c, 128-anchor tile, 64-col tile, pos/neg list). ~600 jobs.
// K in 4 chunks of 64; Ah/Al (16 KB) + Bh/Bl (8 KB) per chunk, double-buffered.
// 8 warps in 4x2; each warp owns a 32x32 output tile.
__global__ __launch_bounds__(256, 2) void k_main() {
    extern __shared__ char dsm_raw[];
    __shared__ int sA[TAJ], sB[TBJ];
    __shared__ int sjob, scnt[NCLS];

    int tid  = threadIdx.x;
    int wid  = tid >> 5;
    int lane = tid & 31;
    int wm   = wid >> 1;          // 0..3 (M: 32 rows each)
    int wn   = wid & 1;           // 0..1 (N: 32 cols each)

    unsigned dynaddr = smem_u32(dsm_raw);
    unsigned base0   = (dynaddr + 1023u) & ~1023u;

    if (tid < NCLS) scnt[tid] = g_cnt[tid];

    // per-lane ldmatrix address components (validated R6/R8)
    const uint32_t aRow = ((lane >> 3) & 1) * 8 + (lane & 7);
    const uint32_t kAh  = ((lane >> 4) & 1) * 16;
    const uint32_t bRow = ((lane >> 4) & 1) * 8 + (lane & 7);
    const uint32_t kBh  = ((lane >> 3) & 1) * 16;
    const uint32_t xm   = (lane & 7) << 4;
    const uint32_t aByte = (wm * 32 + aRow) * 128;
    const uint32_t bByte = (wn * 32 + bRow) * 128;

    // staging geometry: 12 cp.async / thread / chunk.
    // A (hi,lo): row ra = tid>>1, units iua = (tid&1)*4 + 0..3
    // B (hi,lo): row rb = tid>>2, units iub = (tid&3)*2 + 0..1
    const int ra = tid >> 1;
    const int ha = tid & 1;
    const int rb = tid >> 2;
    const int qb = tid & 3;

    for (;;) {
        if (tid == 0) sjob = atomicAdd(&g_ticket, 1);
        __syncthreads();
        int rem = sjob;

        int c = -1, atile = 0, ct = 0, pt = 0;
#pragma unroll
        for (int cc = 0; cc < NCLS; cc++) {
            int at = (scnt[cc] + TAJ - 1) / TAJ;
            int p  = (scnt[cc] + TBJ - 1) / TBJ;
            int n  = (scnt[cc ^ 1] + TBJ - 1) / TBJ;
            int nj = at * (p + n);
            if (c < 0) {
                if (rem < nj) { c = cc; atile = rem / (p + n); ct = rem % (p + n); pt = p; }
                else rem -= nj;
            }
        }
        if (c < 0) break;

        bool isPos = (ct < pt);
        int lc     = isPos ? c : (c ^ 1);
        int cbase  = (isPos ? ct : ct - pt) * TBJ;
        int cntA = scnt[c], cntB = scnt[lc];

        if (tid < TAJ) { int a = atile * TAJ + tid; sA[tid] = (a < cntA) ? g_idx[c][a]  : -1; }
        else if (tid < TAJ + TBJ) {
            int j = cbase + (tid - TAJ);
            sB[tid - TAJ] = (j < cntB) ? g_idx[lc][j] : -1;
        }
        __syncthreads();

        // hoist per-thread staging entries (12 per chunk)
        const char* srcs[12];
        unsigned    ssz[12];
        unsigned    dsts[12];
        {
            int gA = sA[ra], gB = sB[rb];
            const char* pAh = reinterpret_cast<const char*>(g_eh + (size_t)(gA < 0 ? 0 : gA) * H);
            const char* pAl = reinterpret_cast<const char*>(g_el + (size_t)(gA < 0 ? 0 : gA) * H);
            const char* pBh = reinterpret_cast<const char*>(g_eh + (size_t)(gB < 0 ? 0 : gB) * H);
            const char* pBl = reinterpret_cast<const char*>(g_el + (size_t)(gB < 0 ? 0 : gB) * H);
            unsigned szA = (gA >= 0) ? 16u : 0u;
            unsigned szB = (gB >= 0) ? 16u : 0u;
            unsigned swA = ((unsigned)ra & 7) << 4;
            unsigned swB = ((unsigned)rb & 7) << 4;
#pragma unroll
            for (int j = 0; j < 4; j++) {
                unsigned iu = (unsigned)ha * 4 + j;
                unsigned d  = (unsigned)ra * 128 + ((iu * 16) ^ swA);
                srcs[j]     = pAh + iu * 16;  ssz[j]     = szA;  dsts[j]     = d;             // Ah
                srcs[4 + j] = pAl + iu * 16;  ssz[4 + j] = szA;  dsts[4 + j] = MAT_A + d;     // Al
            }
#pragma unroll
            for (int j = 0; j < 2; j++) {
                unsigned iu = (unsigned)qb * 2 + j;
                unsigned d  = (unsigned)rb * 128 + ((iu * 16) ^ swB);
                srcs[8 + j]  = pBh + iu * 16; ssz[8 + j]  = szB; dsts[8 + j]  = 2 * MAT_A + d;          // Bh
                srcs[10 + j] = pBl + iu * 16; ssz[10 + j] = szB; dsts[10 + j] = 2 * MAT_A + MAT_Bb + d; // Bl
            }
        }

        float acc[2][4][4];
#pragma unroll
        for (int mt = 0; mt < 2; mt++)
#pragma unroll
            for (int nt = 0; nt < 4; nt++)
#pragma unroll
                for (int e = 0; e < 4; e++) acc[mt][nt][e] = 0.0f;

        // prologue: issue chunk 0
#pragma unroll
        for (int it = 0; it < 12; it++)
            CP_ASYNC16(base0 + dsts[it], srcs[it], ssz[it]);
        CP_COMMIT();

#pragma unroll 1
        for (int ch = 0; ch < NCH; ch++) {
            if (ch + 1 < NCH) {
                unsigned buf  = base0 + ((unsigned)(ch + 1) & 1u) * BUF_B;
                unsigned koff = (unsigned)(ch + 1) * (KCH * 2);
#pragma unroll
                for (int it = 0; it < 12; it++)
                    CP_ASYNC16(buf + dsts[it], srcs[it] + koff, ssz[it]);
                CP_COMMIT();
                CP_WAIT(1);
            } else {
                CP_WAIT(0);
            }
            __syncthreads();

            unsigned bufc = base0 + ((unsigned)ch & 1u) * BUF_B;
            const uint32_t bAh = bufc;
            const uint32_t bAl = bufc + MAT_A;
            const uint32_t bBh = bufc + 2 * MAT_A;
            const uint32_t bBl = bufc + 2 * MAT_A + MAT_Bb;

#pragma unroll
            for (int kk = 0; kk < 4; kk++) {
                uint32_t kbl = (uint32_t)kk * 32;
                uint32_t koA = (kbl + kAh) ^ xm;
                uint32_t koB = (kbl + kBh) ^ xm;
                uint32_t ah[2][4], al[2][4], bh[4][2], bl[4][2];
#pragma unroll
                for (int mt = 0; mt < 2; mt++) {
                    uint32_t ad = aByte + mt * 2048;
                    LDSM_X4(ah[mt][0], ah[mt][1], ah[mt][2], ah[mt][3], bAh + ad + koA);
                    LDSM_X4(al[mt][0], al[mt][1], al[mt][2], al[mt][3], bAl + ad + koA);
                }
#pragma unroll
                for (int p = 0; p < 2; p++) {
                    uint32_t bd = bByte + p * 2048;
                    LDSM_X4(bh[2*p][0], bh[2*p][1], bh[2*p+1][0], bh[2*p+1][1], bBh + bd + koB);
                    LDSM_X4(bl[2*p][0], bl[2*p][1], bl[2*p+1][0], bl[2*p+1][1], bBl + bd + koB);
                }
#pragma unroll
                for (int mt = 0; mt < 2; mt++)
#pragma unroll
                    for (int nt = 0; nt < 4; nt++) {
                        MMA16816(acc[mt][nt], ah[mt], bh[nt]);
                        MMA16816(acc[mt][nt], ah[mt], bl[nt]);
                        MMA16816(acc[mt][nt], al[mt], bh[nt]);
                    }
            }
            __syncthreads();   // buffer consumed before reuse by chunk ch+2
        }

        // ---- epilogue: fold accumulators to per-anchor min/max ----
        int l4 = lane >> 2, lm = lane & 3;
        int gjc[8];
#pragma unroll
        for (int nt = 0; nt < 4; nt++) {
            int c0 = wn * 32 + nt * 8 + 2 * lm;
            gjc[2*nt]     = sB[c0];
            gjc[2*nt + 1] = sB[c0 + 1];
        }
#pragma unroll
        for (int mt = 0; mt < 2; mt++) {
            int r1 = wm * 32 + mt * 16 + l4;
            int r2 = r1 + 8;
            int gi1 = sA[r1], gi2 = sA[r2];
            float v1 = isPos ? 1e9f : -1e9f;
            float v2 = v1;
#pragma unroll
            for (int nt = 0; nt < 4; nt++) {
                float d0 = acc[mt][nt][0], d1 = acc[mt][nt][1];
                float d2 = acc[mt][nt][2], d3 = acc[mt][nt][3];
                int j0 = gjc[2*nt], j1 = gjc[2*nt + 1];
                if (isPos) {
                    if (j0 >= 0 && j0 != gi1) v1 = fminf(v1, d0);
                    if (j1 >= 0 && j1 != gi1) v1 = fminf(v1, d1);
                    if (j0 >= 0 && j0 != gi2) v2 = fminf(v2, d2);
                    if (j1 >= 0 && j1 != gi2) v2 = fminf(v2, d3);
                } else {
                    if (j0 >= 0) { v1 = fmaxf(v1, d0); v2 = fmaxf(v2, d2); }
                    if (j1 >= 0) { v1 = fmaxf(v1, d1); v2 = fmaxf(v2, d3); }
                }
            }
#pragma unroll
            for (int o = 1; o <= 2; o <<= 1) {
                float o1 = __shfl_xor_sync(0xffffffffu, v1, o);
                float o2 = __shfl_xor_sync(0xffffffffu, v2, o);
                v1 = isPos ? fminf(v1, o1) : fmaxf(v1, o1);
                v2 = isPos ? fminf(v2, o2) : fmaxf(v2, o2);
            }
            if (lm == 0) {
                if (isPos) {
                    if (gi1 >= 0) atomicMin(&g_posmin[gi1], enc_f(v1));
                    if (gi2 >= 0) atomicMin(&g_posmin[gi2], enc_f(v2));
                } else {
                    if (gi1 >= 0) atomicMax(&g_negmax[gi1], enc_f(v1));
                    if (gi2 >= 0) atomicMax(&g_negmax[gi2], enc_f(v2));
                }
            }
        }
        __syncthreads();   // protect sA/sB/smem before next job
    }
}

// ---- K4: per-anchor triplet + deterministic reduction ----
__global__ void k_finalreduce(const void* __restrict__ labv, int N,
                              float* __restrict__ out) {
    __shared__ float ssum[512];
    __shared__ int   snum[512];
    int tid = threadIdx.x;
    int lab64 = sniff_lab64(labv, N);
    float s = 0.0f;
    int   n = 0;
    for (int i = tid; i < N; i += 512) {
        long long l = load_lab(labv, lab64, i);
        if (l >= 1 && l <= 6) {
            int c = (int)l - 1;
            if (g_cnt[c] >= 2 && g_cnt[c ^ 1] >= 1) {
                float hp = dec_f(g_posmin[i]);
                float hn = dec_f(g_negmax[i]);
                s += fmaxf(0.0f, 0.5f + hn - hp);
                n++;
            }
        }
    }
    ssum[tid] = s; snum[tid] = n;
    __syncthreads();
    for (int o = 256; o; o >>= 1) {
        if (tid < o) { ssum[tid] += ssum[tid + o]; snum[tid] += snum[tid + o]; }
        __syncthreads();
    }
    if (tid == 0) out[0] = (snum[0] > 0) ? ssum[0] / (float)snum[0] : 0.0f;
}

extern "C" void kernel_launch(void* const* d_in, const int* in_sizes, int n_in,
                              void* d_out, int out_size) {
    const float* emb = (const float*)d_in[0];
    const void*  lab = d_in[1];
    int N = in_sizes[1];
    if (N > NMAX) N = NMAX;

    cudaFuncSetAttribute(k_main, cudaFuncAttributeMaxDynamicSharedMemorySize, DSMEM);

    k_norm<<<(N + 7) / 8, 256>>>(emb, N);
    k_compact<<<(N + 255) / 256, 256>>>(lab, N);
    k_main<<<304, 256, DSMEM>>>();
    k_finalreduce<<<1, 512>>>(lab, N, (float*)d_out);
}

// round 12
// speedup vs baseline: 1.1793x; 1.1793x over previous
#include <cuda_runtime.h>
#include <cuda_bf16.h>
#include <cstdint>

#define H      256
#define NMAX   8192
#define NCLS   6        // classes 1..6; confused pair of c is c^1 (0-based)
#define TAJ    128      // anchors per job (M)
#define TBJ    64       // cols per job (N)
#define KCH    64       // K elements per staged chunk
#define NCH    4        // chunks per job
#define MAT_A  16384    // bytes per A matrix chunk: 128 rows x 128 B
#define MAT_Bb 8192     // bytes per B matrix chunk: 64 rows x 128 B
#define BUF_B  (2 * MAT_A + 2 * MAT_Bb)   // Ah,Al,Bh,Bl = 48 KB
#define DSMEM  (2 * BUF_B + 1024)         // double-buffered + align slack
#define NPART  64       // partial-reduction blocks

// ---- scratch (static device globals; no dynamic allocation) ----
__device__ __nv_bfloat16 g_eh[NMAX * H];   // hi bf16 of normalized embeddings
__device__ __nv_bfloat16 g_el[NMAX * H];   // lo residual bf16
__device__ int      g_idx[NCLS][NMAX];
__device__ int      g_cnt[NCLS];
__device__ unsigned g_posmin[NMAX];
__device__ unsigned g_negmax[NMAX];
__device__ int      g_ticket;
__device__ float    g_psum[NPART];
__device__ int      g_pcnt[NPART];

__device__ __forceinline__ unsigned enc_f(float f) {
    unsigned u = __float_as_uint(f);
    return (u & 0x80000000u) ? ~u : (u | 0x80000000u);
}
__device__ __forceinline__ float dec_f(unsigned v) {
    return __uint_as_float((v & 0x80000000u) ? (v ^ 0x80000000u) : ~v);
}
__device__ __forceinline__ uint32_t smem_u32(const void* p) {
    uint32_t a;
    asm("{ .reg .u64 t; cvta.to.shared.u64 t, %1; cvt.u32.u64 %0, t; }" : "=r"(a) : "l"(p));
    return a;
}
// label dtype sniff: 1 if int64, 0 if int32
__device__ __forceinline__ int sniff_lab64(const void* labv, int N) {
    const long long* l = reinterpret_cast<const long long*>(labv);
    int n = (N < 16) ? N : 16;
    int ok = 1;
#pragma unroll
    for (int i = 0; i < 16; i++) {
        if (i < n) {
            long long v = l[i];
            if (v < -1000000LL || v > 1000000LL) ok = 0;
        }
    }
    return ok;
}
__device__ __forceinline__ long long load_lab(const void* labv, int lab64, int i) {
    return lab64 ? reinterpret_cast<const long long*>(labv)[i]
                 : (long long)reinterpret_cast<const int*>(labv)[i];
}

#define LDSM_X4(r0, r1, r2, r3, addr) \
    asm volatile("ldmatrix.sync.aligned.m8n8.x4.shared.b16 {%0,%1,%2,%3}, [%4];" \
        : "=r"(r0), "=r"(r1), "=r"(r2), "=r"(r3) : "r"(addr))

#define MMA16816(d, a, b) \
    asm volatile("mma.sync.aligned.m16n8k16.row.col.f32.bf16.bf16.f32 " \
        "{%0,%1,%2,%3}, {%4,%5,%6,%7}, {%8,%9}, {%0,%1,%2,%3};" \
        : "+f"((d)[0]), "+f"((d)[1]), "+f"((d)[2]), "+f"((d)[3]) \
        : "r"((a)[0]), "r"((a)[1]), "r"((a)[2]), "r"((a)[3]), \
          "r"((b)[0]), "r"((b)[1]))

#define CP_ASYNC16(dst, src, srcsize) \
    asm volatile("cp.async.cg.shared.global [%0], [%1], 16, %2;" \
        :: "r"(dst), "l"(src), "r"(srcsize) : "memory")
#define CP_COMMIT()  asm volatile("cp.async.commit_group;" ::: "memory")
#define CP_WAIT(n)   asm volatile("cp.async.wait_group %0;" :: "n"(n) : "memory")

// ---- K1: L2-normalize rows, emit bf16 hi/lo, init min/max; block 0 zeroes counters ----
__global__ void k_norm(const float* __restrict__ emb, int N) {
    if (blockIdx.x == 0) {
        int t = threadIdx.x;
        if (t < NCLS) g_cnt[t] = 0;
        if (t == 30) g_ticket = 0;
    }
    int row  = blockIdx.x * 8 + (threadIdx.x >> 5);
    int lane = threadIdx.x & 31;
    if (row >= N) return;
    const float4* src = reinterpret_cast<const float4*>(emb) + row * (H / 4);
    float4 v0 = src[lane * 2];
    float4 v1 = src[lane * 2 + 1];
    float ss = v0.x*v0.x + v0.y*v0.y + v0.z*v0.z + v0.w*v0.w
             + v1.x*v1.x + v1.y*v1.y + v1.z*v1.z + v1.w*v1.w;
#pragma unroll
    for (int o = 16; o; o >>= 1) ss += __shfl_xor_sync(0xffffffffu, ss, o);
    float s = 1.0f / fmaxf(sqrtf(ss), 1e-12f);
    float f[8] = { v0.x*s, v0.y*s, v0.z*s, v0.w*s, v1.x*s, v1.y*s, v1.z*s, v1.w*s };
    unsigned hw[4], lw[4];
#pragma unroll
    for (int p = 0; p < 4; p++) {
        float a = f[2*p], b = f[2*p+1];
        __nv_bfloat16 ha = __float2bfloat16_rn(a);
        __nv_bfloat16 hb = __float2bfloat16_rn(b);
        __nv_bfloat16 la = __float2bfloat16_rn(a - __bfloat162float(ha));
        __nv_bfloat16 lb = __float2bfloat16_rn(b - __bfloat162float(hb));
        hw[p] = (unsigned)__bfloat16_as_ushort(ha) | ((unsigned)__bfloat16_as_ushort(hb) << 16);
        lw[p] = (unsigned)__bfloat16_as_ushort(la) | ((unsigned)__bfloat16_as_ushort(lb) << 16);
    }
    reinterpret_cast<uint4*>(g_eh)[row * (H / 8) + lane] = make_uint4(hw[0], hw[1], hw[2], hw[3]);
    reinterpret_cast<uint4*>(g_el)[row * (H / 8) + lane] = make_uint4(lw[0], lw[1], lw[2], lw[3]);
    if (lane == 0) {
        g_posmin[row] = enc_f(1e9f);
        g_negmax[row] = enc_f(-1e9f);
    }
}

// ---- K2: compact row indices per class, block-aggregated atomics ----
__global__ void k_compact(const void* __restrict__ labv, int N) {
    __shared__ int hcnt[NCLS];
    __shared__ int hbase[NCLS];
    int tid = threadIdx.x;
    int lab64 = sniff_lab64(labv, N);
    if (tid < NCLS) hcnt[tid] = 0;
    __syncthreads();
    int i = blockIdx.x * 256 + tid;
    int c = -1, p = 0;
    if (i < N) {
        long long l = load_lab(labv, lab64, i);
        if (l >= 1 && l <= 6) {
            c = (int)l - 1;
            p = atomicAdd(&hcnt[c], 1);
        }
    }
    __syncthreads();
    if (tid < NCLS) hbase[tid] = hcnt[tid] ? atomicAdd(&g_cnt[tid], hcnt[tid]) : 0;
    __syncthreads();
    if (c >= 0) g_idx[c][hbase[c] + p] = i;
}

// ---- K3: persistent HMMA GEMM, cp.async double-buffered, 2 CTAs/SM ----
// Job = (class c, 128-anchor tile, 64-col tile, pos/neg list). ~600 jobs.
// K in 4 chunks of 64; Ah/Al (16 KB) + Bh/Bl (8 KB) per chunk, double-buffered.
// 8 warps in 4x2; each warp owns a 32x32 output tile.
__global__ __launch_bounds__(256, 2) void k_main() {
    extern __shared__ char dsm_raw[];
    __shared__ int sA[TAJ], sB[TBJ];
    __shared__ int sjob, scnt[NCLS];

    int tid  = threadIdx.x;
    int wid  = tid >> 5;
    int lane = tid & 31;
    int wm   = wid >> 1;          // 0..3 (M: 32 rows each)
    int wn   = wid & 1;           // 0..1 (N: 32 cols each)

    unsigned dynaddr = smem_u32(dsm_raw);
    unsigned base0   = (dynaddr + 1023u) & ~1023u;

    if (tid < NCLS) scnt[tid] = g_cnt[tid];

    // per-lane ldmatrix address components (validated R6/R8)
    const uint32_t aRow = ((lane >> 3) & 1) * 8 + (lane & 7);
    const uint32_t kAh  = ((lane >> 4) & 1) * 16;
    const uint32_t bRow = ((lane >> 4) & 1) * 8 + (lane & 7);
    const uint32_t kBh  = ((lane >> 3) & 1) * 16;
    const uint32_t xm   = (lane & 7) << 4;
    const uint32_t aByte = (wm * 32 + aRow) * 128;
    const uint32_t bByte = (wn * 32 + bRow) * 128;

    // staging geometry: 12 cp.async / thread / chunk.
    const int ra = tid >> 1;
    const int ha = tid & 1;
    const int rb = tid >> 2;
    const int qb = tid & 3;

    for (;;) {
        if (tid == 0) sjob = atomicAdd(&g_ticket, 1);
        __syncthreads();
        int rem = sjob;

        int c = -1, atile = 0, ct = 0, pt = 0;
#pragma unroll
        for (int cc = 0; cc < NCLS; cc++) {
            int at = (scnt[cc] + TAJ - 1) / TAJ;
            int p  = (scnt[cc] + TBJ - 1) / TBJ;
            int n  = (scnt[cc ^ 1] + TBJ - 1) / TBJ;
            int nj = at * (p + n);
            if (c < 0) {
                if (rem < nj) { c = cc; atile = rem / (p + n); ct = rem % (p + n); pt = p; }
                else rem -= nj;
            }
        }
        if (c < 0) break;

        bool isPos = (ct < pt);
        int lc     = isPos ? c : (c ^ 1);
        int cbase  = (isPos ? ct : ct - pt) * TBJ;
        int cntA = scnt[c], cntB = scnt[lc];

        if (tid < TAJ) { int a = atile * TAJ + tid; sA[tid] = (a < cntA) ? g_idx[c][a]  : -1; }
        else if (tid < TAJ + TBJ) {
            int j = cbase + (tid - TAJ);
            sB[tid - TAJ] = (j < cntB) ? g_idx[lc][j] : -1;
        }
        __syncthreads();

        // hoist per-thread staging entries (12 per chunk)
        const char* srcs[12];
        unsigned    ssz[12];
        unsigned    dsts[12];
        {
            int gA = sA[ra], gB = sB[rb];
            const char* pAh = reinterpret_cast<const char*>(g_eh + (size_t)(gA < 0 ? 0 : gA) * H);
            const char* pAl = reinterpret_cast<const char*>(g_el + (size_t)(gA < 0 ? 0 : gA) * H);
            const char* pBh = reinterpret_cast<const char*>(g_eh + (size_t)(gB < 0 ? 0 : gB) * H);
            const char* pBl = reinterpret_cast<const char*>(g_el + (size_t)(gB < 0 ? 0 : gB) * H);
            unsigned szA = (gA >= 0) ? 16u : 0u;
            unsigned szB = (gB >= 0) ? 16u : 0u;
            unsigned swA = ((unsigned)ra & 7) << 4;
            unsigned swB = ((unsigned)rb & 7) << 4;
#pragma unroll
            for (int j = 0; j < 4; j++) {
                unsigned iu = (unsigned)ha * 4 + j;
                unsigned d  = (unsigned)ra * 128 + ((iu * 16) ^ swA);
                srcs[j]     = pAh + iu * 16;  ssz[j]     = szA;  dsts[j]     = d;             // Ah
                srcs[4 + j] = pAl + iu * 16;  ssz[4 + j] = szA;  dsts[4 + j] = MAT_A + d;     // Al
            }
#pragma unroll
            for (int j = 0; j < 2; j++) {
                unsigned iu = (unsigned)qb * 2 + j;
                unsigned d  = (unsigned)rb * 128 + ((iu * 16) ^ swB);
                srcs[8 + j]  = pBh + iu * 16; ssz[8 + j]  = szB; dsts[8 + j]  = 2 * MAT_A + d;          // Bh
                srcs[10 + j] = pBl + iu * 16; ssz[10 + j] = szB; dsts[10 + j] = 2 * MAT_A + MAT_Bb + d; // Bl
            }
        }

        float acc[2][4][4];
#pragma unroll
        for (int mt = 0; mt < 2; mt++)
#pragma unroll
            for (int nt = 0; nt < 4; nt++)
#pragma unroll
                for (int e = 0; e < 4; e++) acc[mt][nt][e] = 0.0f;

        // prologue: issue chunk 0
#pragma unroll
        for (int it = 0; it < 12; it++)
            CP_ASYNC16(base0 + dsts[it], srcs[it], ssz[it]);
        CP_COMMIT();

#pragma unroll 1
        for (int ch = 0; ch < NCH; ch++) {
            if (ch + 1 < NCH) {
                unsigned buf  = base0 + ((unsigned)(ch + 1) & 1u) * BUF_B;
                unsigned koff = (unsigned)(ch + 1) * (KCH * 2);
#pragma unroll
                for (int it = 0; it < 12; it++)
                    CP_ASYNC16(buf + dsts[it], srcs[it] + koff, ssz[it]);
                CP_COMMIT();
                CP_WAIT(1);
            } else {
                CP_WAIT(0);
            }
            __syncthreads();

            unsigned bufc = base0 + ((unsigned)ch & 1u) * BUF_B;
            const uint32_t bAh = bufc;
            const uint32_t bAl = bufc + MAT_A;
            const uint32_t bBh = bufc + 2 * MAT_A;
            const uint32_t bBl = bufc + 2 * MAT_A + MAT_Bb;

#pragma unroll
            for (int kk = 0; kk < 4; kk++) {
                uint32_t kbl = (uint32_t)kk * 32;
                uint32_t koA = (kbl + kAh) ^ xm;
                uint32_t koB = (kbl + kBh) ^ xm;
                uint32_t ah[2][4], al[2][4], bh[4][2], bl[4][2];
#pragma unroll
                for (int mt = 0; mt < 2; mt++) {
                    uint32_t ad = aByte + mt * 2048;
                    LDSM_X4(ah[mt][0], ah[mt][1], ah[mt][2], ah[mt][3], bAh + ad + koA);
                    LDSM_X4(al[mt][0], al[mt][1], al[mt][2], al[mt][3], bAl + ad + koA);
                }
#pragma unroll
                for (int p = 0; p < 2; p++) {
                    uint32_t bd = bByte + p * 2048;
                    LDSM_X4(bh[2*p][0], bh[2*p][1], bh[2*p+1][0], bh[2*p+1][1], bBh + bd + koB);
                    LDSM_X4(bl[2*p][0], bl[2*p][1], bl[2*p+1][0], bl[2*p+1][1], bBl + bd + koB);
                }
#pragma unroll
                for (int mt = 0; mt < 2; mt++)
#pragma unroll
                    for (int nt = 0; nt < 4; nt++) {
                        MMA16816(acc[mt][nt], ah[mt], bh[nt]);
                        MMA16816(acc[mt][nt], ah[mt], bl[nt]);
                        MMA16816(acc[mt][nt], al[mt], bh[nt]);
                    }
            }
            __syncthreads();   // buffer consumed before reuse by chunk ch+2
        }

        // ---- epilogue: fold accumulators to per-anchor min/max ----
        int l4 = lane >> 2, lm = lane & 3;
        int gjc[8];
#pragma unroll
        for (int nt = 0; nt < 4; nt++) {
            int c0 = wn * 32 + nt * 8 + 2 * lm;
            gjc[2*nt]     = sB[c0];
            gjc[2*nt + 1] = sB[c0 + 1];
        }
#pragma unroll
        for (int mt = 0; mt < 2; mt++) {
            int r1 = wm * 32 + mt * 16 + l4;
            int r2 = r1 + 8;
            int gi1 = sA[r1], gi2 = sA[r2];
            float v1 = isPos ? 1e9f : -1e9f;
            float v2 = v1;
#pragma unroll
            for (int nt = 0; nt < 4; nt++) {
                float d0 = acc[mt][nt][0], d1 = acc[mt][nt][1];
                float d2 = acc[mt][nt][2], d3 = acc[mt][nt][3];
                int j0 = gjc[2*nt], j1 = gjc[2*nt + 1];
                if (isPos) {
                    if (j0 >= 0 && j0 != gi1) v1 = fminf(v1, d0);
                    if (j1 >= 0 && j1 != gi1) v1 = fminf(v1, d1);
                    if (j0 >= 0 && j0 != gi2) v2 = fminf(v2, d2);
                    if (j1 >= 0 && j1 != gi2) v2 = fminf(v2, d3);
                } else {
                    if (j0 >= 0) { v1 = fmaxf(v1, d0); v2 = fmaxf(v2, d2); }
                    if (j1 >= 0) { v1 = fmaxf(v1, d1); v2 = fmaxf(v2, d3); }
                }
            }
#pragma unroll
            for (int o = 1; o <= 2; o <<= 1) {
                float o1 = __shfl_xor_sync(0xffffffffu, v1, o);
                float o2 = __shfl_xor_sync(0xffffffffu, v2, o);
                v1 = isPos ? fminf(v1, o1) : fmaxf(v1, o1);
                v2 = isPos ? fminf(v2, o2) : fmaxf(v2, o2);
            }
            if (lm == 0) {
                if (isPos) {
                    if (gi1 >= 0) atomicMin(&g_posmin[gi1], enc_f(v1));
                    if (gi2 >= 0) atomicMin(&g_posmin[gi2], enc_f(v2));
                } else {
                    if (gi1 >= 0) atomicMax(&g_negmax[gi1], enc_f(v1));
                    if (gi2 >= 0) atomicMax(&g_negmax[gi2], enc_f(v2));
                }
            }
        }
        __syncthreads();   // protect sA/sB/smem before next job
    }
}

// ---- K4a: parallel partial reduction (deterministic partitioning) ----
__global__ void k_partial(const void* __restrict__ labv, int N) {
    __shared__ float ssum[128];
    __shared__ int   snum[128];
    int tid = threadIdx.x;
    int lab64 = sniff_lab64(labv, N);
    int i = blockIdx.x * 128 + tid;
    float s = 0.0f;
    int   n = 0;
    if (i < N) {
        long long l = load_lab(labv, lab64, i);
        if (l >= 1 && l <= 6) {
            int c = (int)l - 1;
            if (g_cnt[c] >= 2 && g_cnt[c ^ 1] >= 1) {
                float hp = dec_f(g_posmin[i]);
                float hn = dec_f(g_negmax[i]);
                s = fmaxf(0.0f, 0.5f + hn - hp);
                n = 1;
            }
        }
    }
    ssum[tid] = s; snum[tid] = n;
    __syncthreads();
#pragma unroll
    for (int o = 64; o; o >>= 1) {
        if (tid < o) { ssum[tid] += ssum[tid + o]; snum[tid] += snum[tid + o]; }
        __syncthreads();
    }
    if (tid == 0) { g_psum[blockIdx.x] = ssum[0]; g_pcnt[blockIdx.x] = snum[0]; }
}

// ---- K4b: fold partials into the scalar loss ----
__global__ void k_final(float* __restrict__ out) {
    __shared__ float ssum[NPART];
    __shared__ int   snum[NPART];
    int tid = threadIdx.x;
    ssum[tid] = g_psum[tid];
    snum[tid] = g_pcnt[tid];
    __syncthreads();
#pragma unroll
    for (int o = NPART / 2; o; o >>= 1) {
        if (tid < o) { ssum[tid] += ssum[tid + o]; snum[tid] += snum[tid + o]; }
        __syncthreads();
    }
    if (tid == 0) out[0] = (snum[0] > 0) ? ssum[0] / (float)snum[0] : 0.0f;
}

extern "C" void kernel_launch(void* const* d_in, const int* in_sizes, int n_in,
                              void* d_out, int out_size) {
    const float* emb = (const float*)d_in[0];
    const void*  lab = d_in[1];
    int N = in_sizes[1];
    if (N > NMAX) N = NMAX;

    cudaFuncSetAttribute(k_main, cudaFuncAttributeMaxDynamicSharedMemorySize, DSMEM);

    k_norm<<<(N + 7) / 8, 256>>>(emb, N);
    k_compact<<<(N + 255) / 256, 256>>>(lab, N);
    k_main<<<304, 256, DSMEM>>>();
    k_partial<<<NPART, 128>>>(lab, N);
    k_final<<<1, NPART>>>((float*)d_out);
}

// round 16
// speedup vs baseline: 1.8064x; 1.5318x over previous
#include <cuda_runtime.h>
#include <cuda_bf16.h>
#include <cstdint>

#define H      256
#define NMAX   8192
#define NCLS   6        // classes 1..6; confused pair of c is c^1 (0-based)
#define TT     64       // square tile (M and N per job)
#define KCH    64       // K elements per staged chunk
#define NCH    4        // chunks per job
#define MAT_T  8192     // bytes per matrix per chunk: 64 rows x 128 B
#define BUF_T  (4 * MAT_T)          // Ah,Al,Bh,Bl = 32 KB
#define DSMEM  (2 * BUF_T + 1024)   // double-buffered + align slack
#define NPART  64       // partial-reduction blocks

// ---- scratch (static device globals; no dynamic allocation) ----
__device__ __nv_bfloat16 g_eh[NMAX * H];   // hi bf16 of normalized embeddings
__device__ __nv_bfloat16 g_el[NMAX * H];   // lo residual bf16
__device__ int      g_idx[NCLS][NMAX];
__device__ int      g_cnt[NCLS];
__device__ unsigned g_posmin[NMAX];
__device__ unsigned g_negmax[NMAX];
__device__ int      g_ticket;
__device__ int      g_lab64;
__device__ float    g_psum[NPART];
__device__ int      g_pcnt[NPART];

__device__ __forceinline__ unsigned enc_f(float f) {
    unsigned u = __float_as_uint(f);
    return (u & 0x80000000u) ? ~u : (u | 0x80000000u);
}
__device__ __forceinline__ float dec_f(unsigned v) {
    return __uint_as_float((v & 0x80000000u) ? (v ^ 0x80000000u) : ~v);
}
__device__ __forceinline__ uint32_t smem_u32(const void* p) {
    uint32_t a;
    asm("{ .reg .u64 t; cvta.to.shared.u64 t, %1; cvt.u32.u64 %0, t; }" : "=r"(a) : "l"(p));
    return a;
}
__device__ __forceinline__ long long load_lab(const void* labv, int lab64, int i) {
    return lab64 ? reinterpret_cast<const long long*>(labv)[i]
                 : (long long)reinterpret_cast<const int*>(labv)[i];
}

#define LDSM_X4(r0, r1, r2, r3, addr) \
    asm volatile("ldmatrix.sync.aligned.m8n8.x4.shared.b16 {%0,%1,%2,%3}, [%4];" \
        : "=r"(r0), "=r"(r1), "=r"(r2), "=r"(r3) : "r"(addr))

#define MMA16816(d, a, b) \
    asm volatile("mma.sync.aligned.m16n8k16.row.col.f32.bf16.bf16.f32 " \
        "{%0,%1,%2,%3}, {%4,%5,%6,%7}, {%8,%9}, {%0,%1,%2,%3};" \
        : "+f"((d)[0]), "+f"((d)[1]), "+f"((d)[2]), "+f"((d)[3]) \
        : "r"((a)[0]), "r"((a)[1]), "r"((a)[2]), "r"((a)[3]), \
          "r"((b)[0]), "r"((b)[1]))

#define CP_ASYNC16(dst, src, srcsize) \
    asm volatile("cp.async.cg.shared.global [%0], [%1], 16, %2;" \
        :: "r"(dst), "l"(src), "r"(srcsize) : "memory")
#define CP_COMMIT()  asm volatile("cp.async.commit_group;" ::: "memory")
#define CP_WAIT(n)   asm volatile("cp.async.wait_group %0;" :: "n"(n) : "memory")

// ---- K1: L2-normalize rows, emit bf16 hi/lo, init min/max; block 0 inits globals ----
__global__ void k_norm(const float* __restrict__ emb,
                       const void* __restrict__ labv, int N) {
    if (blockIdx.x == 0) {
        int t = threadIdx.x;
        if (t < NCLS) g_cnt[t] = 0;
        if (t == 30) g_ticket = 0;
        if (t == 31) {   // label dtype sniff, once
            const long long* l = reinterpret_cast<const long long*>(labv);
            int n = (N < 16) ? N : 16;
            int ok = 1;
            for (int i = 0; i < n; i++) {
                long long v = l[i];
                if (v < -1000000LL || v > 1000000LL) ok = 0;
            }
            g_lab64 = ok;
        }
    }
    int row  = blockIdx.x * 8 + (threadIdx.x >> 5);
    int lane = threadIdx.x & 31;
    if (row >= N) return;
    const float4* src = reinterpret_cast<const float4*>(emb) + row * (H / 4);
    float4 v0 = src[lane * 2];
    float4 v1 = src[lane * 2 + 1];
    float ss = v0.x*v0.x + v0.y*v0.y + v0.z*v0.z + v0.w*v0.w
             + v1.x*v1.x + v1.y*v1.y + v1.z*v1.z + v1.w*v1.w;
#pragma unroll
    for (int o = 16; o; o >>= 1) ss += __shfl_xor_sync(0xffffffffu, ss, o);
    float s = 1.0f / fmaxf(sqrtf(ss), 1e-12f);
    float f[8] = { v0.x*s, v0.y*s, v0.z*s, v0.w*s, v1.x*s, v1.y*s, v1.z*s, v1.w*s };
    unsigned hw[4], lw[4];
#pragma unroll
    for (int p = 0; p < 4; p++) {
        float a = f[2*p], b = f[2*p+1];
        __nv_bfloat16 ha = __float2bfloat16_rn(a);
        __nv_bfloat16 hb = __float2bfloat16_rn(b);
        __nv_bfloat16 la = __float2bfloat16_rn(a - __bfloat162float(ha));
        __nv_bfloat16 lb = __float2bfloat16_rn(b - __bfloat162float(hb));
        hw[p] = (unsigned)__bfloat16_as_ushort(ha) | ((unsigned)__bfloat16_as_ushort(hb) << 16);
        lw[p] = (unsigned)__bfloat16_as_ushort(la) | ((unsigned)__bfloat16_as_ushort(lb) << 16);
    }
    reinterpret_cast<uint4*>(g_eh)[row * (H / 8) + lane] = make_uint4(hw[0], hw[1], hw[2], hw[3]);
    reinterpret_cast<uint4*>(g_el)[row * (H / 8) + lane] = make_uint4(lw[0], lw[1], lw[2], lw[3]);
    if (lane == 0) {
        g_posmin[row] = enc_f(1e9f);
        g_negmax[row] = enc_f(-1e9f);
    }
}

// ---- K2: compact row indices per class, block-aggregated atomics ----
__global__ void k_compact(const void* __restrict__ labv, int N) {
    __shared__ int hcnt[NCLS];
    __shared__ int hbase[NCLS];
    int tid = threadIdx.x;
    int lab64 = g_lab64;
    if (tid < NCLS) hcnt[tid] = 0;
    __syncthreads();
    int i = blockIdx.x * 256 + tid;
    int c = -1, p = 0;
    if (i < N) {
        long long l = load_lab(labv, lab64, i);
        if (l >= 1 && l <= 6) {
            c = (int)l - 1;
            p = atomicAdd(&hcnt[c], 1);
        }
    }
    __syncthreads();
    if (tid < NCLS) hbase[tid] = hcnt[tid] ? atomicAdd(&g_cnt[tid], hcnt[tid]) : 0;
    __syncthreads();
    if (c >= 0) g_idx[c][hbase[c] + p] = i;
}

// ---- K3: persistent HMMA GEMM exploiting Gram symmetry ----
// Pos jobs: class c, 64-tile pairs (i <= j); diagonal = self-excluded row fold,
// cross tiles fold rows (tile i anchors) AND columns (tile j anchors).
// Neg jobs: pairs (c, c+1) c even, all (i, j); row fold -> c anchors,
// col fold -> c+1 anchors. ~630 jobs of 64x64, 3 CTAs/SM.
__global__ __launch_bounds__(256, 3) void k_main() {
    extern __shared__ char dsm_raw[];
    __shared__ int sA[TT], sB[TT];
    __shared__ int sjob, scnt[NCLS];

    int tid  = threadIdx.x;
    int wid  = tid >> 5;
    int lane = tid & 31;
    int wm   = wid >> 2;          // 0..1 (M: 32 rows each)
    int wn   = wid & 3;           // 0..3 (N: 16 cols each)

    unsigned dynaddr = smem_u32(dsm_raw);
    unsigned base0   = (dynaddr + 1023u) & ~1023u;

    if (tid < NCLS) scnt[tid] = g_cnt[tid];

    // per-lane ldmatrix address components (validated R6/R8/R12)
    const uint32_t aRow = ((lane >> 3) & 1) * 8 + (lane & 7);
    const uint32_t kAh  = ((lane >> 4) & 1) * 16;
    const uint32_t bRow = ((lane >> 4) & 1) * 8 + (lane & 7);
    const uint32_t kBh  = ((lane >> 3) & 1) * 16;
    const uint32_t xm   = (lane & 7) << 4;
    const uint32_t aByte = (wm * 32 + aRow) * 128;
    const uint32_t bByte = (wn * 16 + bRow) * 128;

    // staging: 8 cp.async / thread / chunk. row r = tid>>2, units 2q,2q+1.
    const int rs = tid >> 2;
    const int qs = tid & 3;

    for (;;) {
        if (tid == 0) sjob = atomicAdd(&g_ticket, 1);
        __syncthreads();
        int rem = sjob;

        int c = -1, ti = 0, tj = 0;
        bool isPos = false;
        for (int cc = 0; cc < NCLS && c < 0; cc++) {
            int ntc  = (scnt[cc] + TT - 1) / TT;
            int npos = ntc * (ntc + 1) / 2;
            if (rem < npos) {
                c = cc; isPos = true;
                int t = rem, i = 0, row = ntc;
                while (t >= row) { t -= row; i++; row--; }
                ti = i; tj = i + t;
                break;
            }
            rem -= npos;
            if ((cc & 1) == 0) {
                int ntn = (scnt[cc + 1] + TT - 1) / TT;
                int nn  = ntc * ntn;
                if (rem < nn) {
                    c = cc; isPos = false;
                    ti = rem / ntn; tj = rem % ntn;
                    break;
                }
                rem -= nn;
            }
        }
        if (c < 0) break;

        int  lc     = isPos ? c : (c + 1);
        bool isDiag = isPos && (ti == tj);
        int cntA = scnt[c], cntB = scnt[lc];

        if (tid < TT)      { int a = ti * TT + tid;        sA[tid]      = (a < cntA) ? g_idx[c][a]  : -1; }
        else if (tid < 2*TT) { int j = tj * TT + (tid-TT); sB[tid - TT] = (j < cntB) ? g_idx[lc][j] : -1; }
        __syncthreads();

        // hoist per-thread staging entries (8 per chunk)
        const char* srcs[8];
        unsigned    ssz[8];
        unsigned    dsts[8];
        {
            int gA = sA[rs], gB = sB[rs];
            const char* pAh = reinterpret_cast<const char*>(g_eh + (size_t)(gA < 0 ? 0 : gA) * H);
            const char* pAl = reinterpret_cast<const char*>(g_el + (size_t)(gA < 0 ? 0 : gA) * H);
            const char* pBh = reinterpret_cast<const char*>(g_eh + (size_t)(gB < 0 ? 0 : gB) * H);
            const char* pBl = reinterpret_cast<const char*>(g_el + (size_t)(gB < 0 ? 0 : gB) * H);
            unsigned szA = (gA >= 0) ? 16u : 0u;
            unsigned szB = (gB >= 0) ? 16u : 0u;
            unsigned sw  = ((unsigned)rs & 7) << 4;
#pragma unroll
            for (int j = 0; j < 2; j++) {
                unsigned iu = (unsigned)qs * 2 + j;
                unsigned d  = (unsigned)rs * 128 + ((iu * 16) ^ sw);
                srcs[j]     = pAh + iu * 16;  ssz[j]     = szA;  dsts[j]     = d;                 // Ah
                srcs[2 + j] = pAl + iu * 16;  ssz[2 + j] = szA;  dsts[2 + j] = MAT_T + d;         // Al
                srcs[4 + j] = pBh + iu * 16;  ssz[4 + j] = szB;  dsts[4 + j] = 2 * MAT_T + d;     // Bh
                srcs[6 + j] = pBl + iu * 16;  ssz[6 + j] = szB;  dsts[6 + j] = 3 * MAT_T + d;     // Bl
            }
        }

        float acc[2][2][4];
#pragma unroll
        for (int mt = 0; mt < 2; mt++)
#pragma unroll
            for (int nt = 0; nt < 2; nt++)
#pragma unroll
                for (int e = 0; e < 4; e++) acc[mt][nt][e] = 0.0f;

        // prologue: issue chunk 0
#pragma unroll
        for (int it = 0; it < 8; it++)
            CP_ASYNC16(base0 + dsts[it], srcs[it], ssz[it]);
        CP_COMMIT();

#pragma unroll 1
        for (int ch = 0; ch < NCH; ch++) {
            if (ch + 1 < NCH) {
                unsigned buf  = base0 + ((unsigned)(ch + 1) & 1u) * BUF_T;
                unsigned koff = (unsigned)(ch + 1) * (KCH * 2);
#pragma unroll
                for (int it = 0; it < 8; it++)
                    CP_ASYNC16(buf + dsts[it], srcs[it] + koff, ssz[it]);
                CP_COMMIT();
                CP_WAIT(1);
            } else {
                CP_WAIT(0);
            }
            __syncthreads();

            unsigned bufc = base0 + ((unsigned)ch & 1u) * BUF_T;
            const uint32_t bAh = bufc;
            const uint32_t bAl = bufc + MAT_T;
            const uint32_t bBh = bufc + 2 * MAT_T;
            const uint32_t bBl = bufc + 3 * MAT_T;

#pragma unroll
            for (int kk = 0; kk < 4; kk++) {
                uint32_t kbl = (uint32_t)kk * 32;
                uint32_t koA = (kbl + kAh) ^ xm;
                uint32_t koB = (kbl + kBh) ^ xm;
                uint32_t ah[2][4], al[2][4], bh[2][2], bl[2][2];
#pragma unroll
                for (int mt = 0; mt < 2; mt++) {
                    uint32_t ad = aByte + mt * 2048;
                    LDSM_X4(ah[mt][0], ah[mt][1], ah[mt][2], ah[mt][3], bAh + ad + koA);
                    LDSM_X4(al[mt][0], al[mt][1], al[mt][2], al[mt][3], bAl + ad + koA);
                }
                LDSM_X4(bh[0][0], bh[0][1], bh[1][0], bh[1][1], bBh + bByte + koB);
                LDSM_X4(bl[0][0], bl[0][1], bl[1][0], bl[1][1], bBl + bByte + koB);
#pragma unroll
                for (int mt = 0; mt < 2; mt++)
#pragma unroll
                    for (int nt = 0; nt < 2; nt++) {
                        MMA16816(acc[mt][nt], ah[mt], bh[nt]);
                        MMA16816(acc[mt][nt], ah[mt], bl[nt]);
                        MMA16816(acc[mt][nt], al[mt], bh[nt]);
                    }
            }
            __syncthreads();   // buffer consumed before reuse by chunk ch+2
        }

        // ---- epilogue ----
        int l4 = lane >> 2, lm = lane & 3;
        float sent = isPos ? 1e9f : -1e9f;
        int giA[2][2];
#pragma unroll
        for (int mt = 0; mt < 2; mt++) {
            giA[mt][0] = sA[wm * 32 + mt * 16 + l4];
            giA[mt][1] = sA[wm * 32 + mt * 16 + l4 + 8];
        }
        int gjc[4];
#pragma unroll
        for (int nt = 0; nt < 2; nt++) {
            int c0 = wn * 16 + nt * 8 + 2 * lm;
            gjc[2*nt]     = sB[c0];
            gjc[2*nt + 1] = sB[c0 + 1];
        }

        // row fold -> A anchors (index compare handles diagonal self-exclusion;
        // off-diagonal tiles have disjoint index sets so the compare is inert)
#pragma unroll
        for (int mt = 0; mt < 2; mt++) {
            int gi1 = giA[mt][0], gi2 = giA[mt][1];
            float v1 = sent, v2 = sent;
#pragma unroll
            for (int nt = 0; nt < 2; nt++) {
                float d0 = acc[mt][nt][0], d1 = acc[mt][nt][1];
                float d2 = acc[mt][nt][2], d3 = acc[mt][nt][3];
                int j0 = gjc[2*nt], j1 = gjc[2*nt + 1];
                if (isPos) {
                    if (j0 >= 0 && j0 != gi1) v1 = fminf(v1, d0);
                    if (j1 >= 0 && j1 != gi1) v1 = fminf(v1, d1);
                    if (j0 >= 0 && j0 != gi2) v2 = fminf(v2, d2);
                    if (j1 >= 0 && j1 != gi2) v2 = fminf(v2, d3);
                } else {
                    if (j0 >= 0) { v1 = fmaxf(v1, d0); v2 = fmaxf(v2, d2); }
                    if (j1 >= 0) { v1 = fmaxf(v1, d1); v2 = fmaxf(v2, d3); }
                }
            }
#pragma unroll
            for (int o = 1; o <= 2; o <<= 1) {
                float o1 = __shfl_xor_sync(0xffffffffu, v1, o);
                float o2 = __shfl_xor_sync(0xffffffffu, v2, o);
                v1 = isPos ? fminf(v1, o1) : fmaxf(v1, o1);
                v2 = isPos ? fminf(v2, o2) : fmaxf(v2, o2);
            }
            if (lm == 0) {
                if (isPos) {
                    if (gi1 >= 0) atomicMin(&g_posmin[gi1], enc_f(v1));
                    if (gi2 >= 0) atomicMin(&g_posmin[gi2], enc_f(v2));
                } else {
                    if (gi1 >= 0) atomicMax(&g_negmax[gi1], enc_f(v1));
                    if (gi2 >= 0) atomicMax(&g_negmax[gi2], enc_f(v2));
                }
            }
        }

        // col fold -> B anchors (cross tiles only; self-pairs impossible there)
        if (!isDiag) {
#pragma unroll
            for (int nt = 0; nt < 2; nt++) {
#pragma unroll
                for (int e = 0; e < 2; e++) {
                    float v = sent;
#pragma unroll
                    for (int mt = 0; mt < 2; mt++) {
                        float w1 = acc[mt][nt][e];       // row l4
                        float w2 = acc[mt][nt][e + 2];   // row l4+8
                        if (giA[mt][0] >= 0) v = isPos ? fminf(v, w1) : fmaxf(v, w1);
                        if (giA[mt][1] >= 0) v = isPos ? fminf(v, w2) : fmaxf(v, w2);
                    }
#pragma unroll
                    for (int o = 4; o <= 16; o <<= 1) {
                        float ov = __shfl_xor_sync(0xffffffffu, v, o);
                        v = isPos ? fminf(v, ov) : fmaxf(v, ov);
                    }
                    if (l4 == 0) {
                        int gj = gjc[2*nt + e];
                        if (gj >= 0) {
                            if (isPos) atomicMin(&g_posmin[gj], enc_f(v));
                            else       atomicMax(&g_negmax[gj], enc_f(v));
                        }
                    }
                }
            }
        }
        __syncthreads();   // protect sA/sB/smem before next job
    }
}

// ---- K4a: parallel partial reduction (deterministic partitioning) ----
__global__ void k_partial(const void* __restrict__ labv, int N) {
    __shared__ float ssum[128];
    __shared__ int   snum[128];
    int tid = threadIdx.x;
    int lab64 = g_lab64;
    int i = blockIdx.x * 128 + tid;
    float s = 0.0f;
    int   n = 0;
    if (i < N) {
        long long l = load_lab(labv, lab64, i);
        if (l >= 1 && l <= 6) {
            int c = (int)l - 1;
            if (g_cnt[c] >= 2 && g_cnt[c ^ 1] >= 1) {
                float hp = dec_f(g_posmin[i]);
                float hn = dec_f(g_negmax[i]);
                s = fmaxf(0.0f, 0.5f + hn - hp);
                n = 1;
            }
        }
    }
    ssum[tid] = s; snum[tid] = n;
    __syncthreads();
#pragma unroll
    for (int o = 64; o; o >>= 1) {
        if (tid < o) { ssum[tid] += ssum[tid + o]; snum[tid] += snum[tid + o]; }
        __syncthreads();
    }
    if (tid == 0) { g_psum[blockIdx.x] = ssum[0]; g_pcnt[blockIdx.x] = snum[0]; }
}

// ---- K4b: fold partials into the scalar loss ----
__global__ void k_final(float* __restrict__ out) {
    __shared__ float ssum[NPART];
    __shared__ int   snum[NPART];
    int tid = threadIdx.x;
    ssum[tid] = g_psum[tid];
    snum[tid] = g_pcnt[tid];
    __syncthreads();
#pragma unroll
    for (int o = NPART / 2; o; o >>= 1) {
        if (tid < o) { ssum[tid] += ssum[tid + o]; snum[tid] += snum[tid + o]; }
        __syncthreads();
    }
    if (tid == 0) out[0] = (snum[0] > 0) ? ssum[0] / (float)snum[0] : 0.0f;
}

extern "C" void kernel_launch(void* const* d_in, const int* in_sizes, int n_in,
                              void* d_out, int out_size) {
    const float* emb = (const float*)d_in[0];
    const void*  lab = d_in[1];
    int N = in_sizes[1];
    if (N > NMAX) N = NMAX;

    cudaFuncSetAttribute(k_main, cudaFuncAttributeMaxDynamicSharedMemorySize, DSMEM);

    k_norm<<<(N + 7) / 8, 256>>>(emb, lab, N);
    k_compact<<<(N + 255) / 256, 256>>>(lab, N);
    k_main<<<456, 256, DSMEM>>>();
    k_partial<<<NPART, 128>>>(lab, N);
    k_final<<<1, NPART>>>((float*)d_out);
}